// round 10
// baseline (speedup 1.0000x reference)
#include <cuda_runtime.h>
#include <cuda_fp16.h>
#include <cstdint>

// Problem constants (fixed by the dataset)
#define H 128
#define TT 4095          // (8192-3)/2 + 1
#define NC 128           // scan chunks
#define LC 32            // chunk length (last chunk = 31)
#define NELEM (H * H)    // 16384 state elements
#define ZSH 136          // padded Zs row stride in halves (conflict-free)

// Scratch (allocation-free rule: __device__ globals)
static __device__ float g_Y[TT * 3 * H];   // Y[t][w][d] = (w_q @ X_t)[w,d]
static __device__ float g_S[NC * NELEM];   // chunk-local end states
static __device__ float g_cin[NC * NELEM]; // carry-in per chunk

static __device__ __forceinline__ uint32_t smem_u32(const void* p) {
    uint32_t a;
    asm("{ .reg .u64 t; cvta.to.shared.u64 t, %1; cvt.u32.u64 %0, t; }"
        : "=r"(a) : "l"(p));
    return a;
}

// ---------------------------------------------------------------------------
// Kernel 1: Y[t][w][:] = sum_v wq[w][v]*x[2t+v][:], os[t][:] = sum_w D[w]*x[2t+w][:]
// ---------------------------------------------------------------------------
__global__ void prep_kernel(const float* __restrict__ in,
                            const float* __restrict__ wq,
                            const float* __restrict__ Dv,
                            float* __restrict__ os_out) {
    int t = blockIdx.x;
    int d = threadIdx.x;
    float x0 = in[(2 * t + 0) * H + d];
    float x1 = in[(2 * t + 1) * H + d];
    float x2 = in[(2 * t + 2) * H + d];
    g_Y[(t * 3 + 0) * H + d] = wq[0] * x0 + wq[1] * x1 + wq[2] * x2;
    g_Y[(t * 3 + 1) * H + d] = wq[3] * x0 + wq[4] * x1 + wq[5] * x2;
    g_Y[(t * 3 + 2) * H + d] = wq[6] * x0 + wq[7] * x1 + wq[8] * x2;
    os_out[t * H + d] = Dv[0] * x0 + Dv[1] * x1 + Dv[2] * x2;
}

// ---------------------------------------------------------------------------
// Kernel 2: chunk-local scan (zero init), double-buffered Y prefetch,
// Xt triplet layout (one LDS.128 per (tl, a)).
// ---------------------------------------------------------------------------
__global__ __launch_bounds__(256) void scan0_kernel(const float* __restrict__ in,
                                                    const float* __restrict__ Lam) {
    __shared__ float Ys[2][8 * 384];
    __shared__ float Xt[LC * 16 * 4];   // [tl][a_local][w0..w2, pad]

    int c   = blockIdx.y;
    int a0  = blockIdx.x * 16;
    int tid = threadIdx.x;
    int d   = tid & 127;
    int ah  = (tid >> 7) * 8;

    int t0c = c * LC;
    int t1c = t0c + LC; if (t1c > TT) t1c = TT;
    int nb  = (t1c - t0c + 7) >> 3;   // always 4
    int ntl = t1c - t0c;              // valid tl count

    // prologue: prefetch Y(0); stage X triplets for whole chunk
    {
        int nvt0 = t1c - t0c; if (nvt0 > 8) nvt0 = 8;
        uint32_t ydst = smem_u32(Ys[0]);
        const float* ysrc = g_Y + t0c * 384;
        for (int i = tid; i < nvt0 * 96; i += 256)
            asm volatile("cp.async.ca.shared.global [%0], [%1], 16;"
                         :: "r"(ydst + i * 16), "l"(ysrc + i * 4));
        asm volatile("cp.async.commit_group;");
    }
    // Xt layout: 64 slots per tl (16 a x 4). w==3 is padding (zero).
    for (int i = tid; i < ntl * 64; i += 256) {
        int tl = i >> 6, r = i & 63, al = r >> 2, w = r & 3;
        Xt[(tl * 16 + al) * 4 + w] =
            (w < 3) ? in[(size_t)(2 * (t0c + tl) + w) * H + a0 + al] : 0.0f;
    }

    float z[8], lam[8];
#pragma unroll
    for (int k = 0; k < 8; k++) {
        lam[k] = Lam[(a0 + ah + k) * H + d];
        z[k]   = 0.0f;
    }

    for (int e = 0; e < nb; e++) {
        asm volatile("cp.async.wait_group 0;");
        __syncthreads();
        if (e + 1 < nb) {
            int tb1  = t0c + (e + 1) * 8;
            int nvt1 = t1c - tb1; if (nvt1 > 8) nvt1 = 8;
            uint32_t ydst = smem_u32(Ys[(e + 1) & 1]);
            const float* ysrc = g_Y + tb1 * 384;
            for (int i = tid; i < nvt1 * 96; i += 256)
                asm volatile("cp.async.ca.shared.global [%0], [%1], 16;"
                             :: "r"(ydst + i * 16), "l"(ysrc + i * 4));
            asm volatile("cp.async.commit_group;");
        }
        int tb  = t0c + e * 8;
        int nvt = t1c - tb; if (nvt > 8) nvt = 8;
        const float* Yb = Ys[e & 1];
        for (int tl = 0; tl < nvt; tl++) {
            float y0 = Yb[tl * 384 + d];
            float y1 = Yb[tl * 384 + 128 + d];
            float y2 = Yb[tl * 384 + 256 + d];
            int tli = tb - t0c + tl;
#pragma unroll
            for (int k = 0; k < 8; k++) {
                float4 xv = *(const float4*)&Xt[(tli * 16 + ah + k) * 4];
                float u = xv.x * y0 + xv.y * y1 + xv.z * y2;
                z[k] = fmaf(lam[k], z[k], u);
            }
        }
    }

#pragma unroll
    for (int k = 0; k < 8; k++) g_S[c * NELEM + (a0 + ah + k) * H + d] = z[k];
}

// ---------------------------------------------------------------------------
// Kernel 3: sequential carry combine across chunks.
// ---------------------------------------------------------------------------
__global__ void combine_kernel(const float* __restrict__ Lam) {
    int e = blockIdx.x * 256 + threadIdx.x;
    float lam = Lam[e];
    float p = lam;  // lam^32 via 5 squarings
    p = p * p; p = p * p; p = p * p; p = p * p; p = p * p;
    float cin = 0.0f;
    for (int c = 0; c < NC; c++) {
        g_cin[c * NELEM + e] = cin;
        cin = fmaf(p, cin, g_S[c * NELEM + e]);
    }
}

// ---------------------------------------------------------------------------
// Kernel 4: FUSED scan + GEMM (all warps both phases, double-buffered Ys+Zs,
// one barrier per epoch, Y prefetch under previous GEMM).
//   scan: 4a x 2d per thread; X via one broadcast LDS.128 per (tl,j).
//   gemm: 4(m)x2(n) warp tiles; B fragments via ldmatrix.m8n8.x4 (2 kt per
//         instruction); C A-frags register-resident. Numerics identical to R8.
// ---------------------------------------------------------------------------
__global__ __launch_bounds__(256, 2) void fused_kernel(const float* __restrict__ in,
                                                       const float* __restrict__ Lam,
                                                       const float* __restrict__ Cm,
                                                       float* __restrict__ out) {
    extern __shared__ float smem[];
    __half* ZsA  = (__half*)smem;                 // 128*ZSH halves
    __half* ZsB  = ZsA + 128 * ZSH;
    float*  YsA  = (float*)(ZsB + 128 * ZSH);     // 8*384 floats
    float*  YsB  = YsA + 8 * 384;
    float*  Xt   = YsB + 8 * 384;                 // LC*16*4 floats

    int tid = threadIdx.x;
    int c   = blockIdx.y;
    int a0  = blockIdx.x * 16;
    int wrp = tid >> 5, l = tid & 31;

    int t0c = c * LC;
    int t1c = t0c + LC; if (t1c > TT) t1c = TT;
    int nb  = (t1c - t0c + 7) >> 3;   // always 4
    int ntl = t1c - t0c;

    // scan mapping: 4 a x 2 d
    int d2 = tid & 63;
    int ag = tid >> 6;

    // gemm mapping
    int grp = l >> 2, thr = l & 3;
    int mg  = wrp & 3, ng = wrp >> 2;
    int h0  = mg * 32;
    // ldmatrix lane offset (bytes): row = l&7 (stride ZSH halves), matrix = l>>3
    uint32_t lmoff = (uint32_t)((l & 7) * ZSH * 2 + (l >> 3) * 16);

    // prologue: prefetch Y(0); stage Xt
    {
        int nvt0 = t1c - t0c; if (nvt0 > 8) nvt0 = 8;
        uint32_t ydst = smem_u32(YsA);
        const float* ysrc = g_Y + t0c * 384;
        for (int i = tid; i < nvt0 * 96; i += 256)
            asm volatile("cp.async.ca.shared.global [%0], [%1], 16;"
                         :: "r"(ydst + i * 16), "l"(ysrc + i * 4));
        asm volatile("cp.async.commit_group;");
    }
    // Xt layout: 64 slots per tl (16 a x 4). w==3 is padding (zero).
    for (int i = tid; i < ntl * 64; i += 256) {
        int tl = i >> 6, r = i & 63, al = r >> 2, w = r & 3;
        Xt[(tl * 16 + al) * 4 + w] =
            (w < 3) ? in[(size_t)(2 * (t0c + tl) + w) * H + a0 + al] : 0.0f;
    }

    // A fragments: C rows [h0,h0+32), fp16. 8 k-tiles x 8 half2 regs.
    uint32_t afr[8][8];
#pragma unroll
    for (int kt = 0; kt < 8; kt++) {
        int cb = kt * 16 + 2 * thr;
#pragma unroll
        for (int mt = 0; mt < 2; mt++) {
            const float* r0 = Cm + (h0 + mt * 16 + grp) * H;
            const float* r1 = Cm + (h0 + mt * 16 + grp + 8) * H;
            __half2 p0 = __floats2half2_rn(r0[cb],     r0[cb + 1]);
            __half2 p1 = __floats2half2_rn(r1[cb],     r1[cb + 1]);
            __half2 p2 = __floats2half2_rn(r0[cb + 8], r0[cb + 9]);
            __half2 p3 = __floats2half2_rn(r1[cb + 8], r1[cb + 9]);
            afr[kt][mt * 4 + 0] = *(uint32_t*)&p0;
            afr[kt][mt * 4 + 1] = *(uint32_t*)&p1;
            afr[kt][mt * 4 + 2] = *(uint32_t*)&p2;
            afr[kt][mt * 4 + 3] = *(uint32_t*)&p3;
        }
    }

    // scan state: 4 a x 2 d per thread
    float z[8], lam[8];
#pragma unroll
    for (int j = 0; j < 4; j++) {
        int a = a0 + ag * 4 + j;
        float2 lv = *(const float2*)&Lam[a * H + 2 * d2];
        float2 cv = *(const float2*)&g_cin[c * NELEM + a * H + 2 * d2];
        lam[j * 2]     = lv.x;  lam[j * 2 + 1] = lv.y;
        z[j * 2]       = cv.x;  z[j * 2 + 1]   = cv.y;
    }

    for (int e = 0; e <= nb; e++) {
        asm volatile("cp.async.wait_group 0;");
        __syncthreads();

        if (e < nb) {
            if (e + 1 < nb) {
                int tb1  = t0c + (e + 1) * 8;
                int nvt1 = t1c - tb1; if (nvt1 > 8) nvt1 = 8;
                uint32_t ydst = smem_u32((e + 1) & 1 ? YsB : YsA);
                const float* ysrc = g_Y + tb1 * 384;
                for (int i = tid; i < nvt1 * 96; i += 256)
                    asm volatile("cp.async.ca.shared.global [%0], [%1], 16;"
                                 :: "r"(ydst + i * 16), "l"(ysrc + i * 4));
                asm volatile("cp.async.commit_group;");
            }

            // ---- scan epoch e -> Zs[e&1] ----
            int tb  = t0c + e * 8;
            int nvt = t1c - tb; if (nvt > 8) nvt = 8;
            const float* Yb = (e & 1) ? YsB : YsA;
            __half* Zb = (e & 1) ? ZsB : ZsA;
            for (int tl = 0; tl < nvt; tl++) {
                float2 y0 = *(const float2*)&Yb[tl * 384 + 2 * d2];
                float2 y1 = *(const float2*)&Yb[tl * 384 + 128 + 2 * d2];
                float2 y2 = *(const float2*)&Yb[tl * 384 + 256 + 2 * d2];
                int tli = tb - t0c + tl;
#pragma unroll
                for (int j = 0; j < 4; j++) {
                    float4 xv = *(const float4*)&Xt[(tli * 16 + ag * 4 + j) * 4];
                    float u0 = xv.x * y0.x + xv.y * y1.x + xv.z * y2.x;
                    float u1 = xv.x * y0.y + xv.y * y1.y + xv.z * y2.y;
                    z[j * 2]     = fmaf(lam[j * 2],     z[j * 2],     u0);
                    z[j * 2 + 1] = fmaf(lam[j * 2 + 1], z[j * 2 + 1], u1);
                    *(__half2*)&Zb[(tl * 16 + ag * 4 + j) * ZSH + 2 * d2] =
                        __floats2half2_rn(z[j * 2], z[j * 2 + 1]);
                }
            }
        }

        // ---- gemm epoch e-1 <- Zs[(e-1)&1] ----
        if (e > 0) {
            int jb = e - 1;
            int tb = t0c + jb * 8;
            const __half* Zb = (jb & 1) ? ZsB : ZsA;
            uint32_t zbase = smem_u32(Zb) + lmoff;
            for (int nt = ng * 8; nt < ng * 8 + 8; nt++) {
                int t = tb + (nt >> 1);
                if (t >= TT) break;
                float acc[8];
#pragma unroll
                for (int i = 0; i < 8; i++) acc[i] = 0.0f;
                uint32_t zrow = zbase + (uint32_t)(nt * 8 * ZSH * 2);
#pragma unroll
                for (int kp = 0; kp < 4; kp++) {   // 2 kt per ldmatrix.x4
                    uint32_t b[4];
                    asm volatile(
                        "ldmatrix.sync.aligned.m8n8.x4.shared.b16 "
                        "{%0,%1,%2,%3}, [%4];"
                        : "=r"(b[0]), "=r"(b[1]), "=r"(b[2]), "=r"(b[3])
                        : "r"(zrow + (uint32_t)(kp * 64)));
                    int kt = kp * 2;
                    asm volatile(
                        "mma.sync.aligned.m16n8k16.row.col.f32.f16.f16.f32 "
                        "{%0,%1,%2,%3}, {%4,%5,%6,%7}, {%8,%9}, {%0,%1,%2,%3};"
                        : "+f"(acc[0]), "+f"(acc[1]), "+f"(acc[2]), "+f"(acc[3])
                        : "r"(afr[kt][0]), "r"(afr[kt][1]), "r"(afr[kt][2]),
                          "r"(afr[kt][3]), "r"(b[0]), "r"(b[1]));
                    asm volatile(
                        "mma.sync.aligned.m16n8k16.row.col.f32.f16.f16.f32 "
                        "{%0,%1,%2,%3}, {%4,%5,%6,%7}, {%8,%9}, {%0,%1,%2,%3};"
                        : "+f"(acc[4]), "+f"(acc[5]), "+f"(acc[6]), "+f"(acc[7])
                        : "r"(afr[kt][4]), "r"(afr[kt][5]), "r"(afr[kt][6]),
                          "r"(afr[kt][7]), "r"(b[0]), "r"(b[1]));
                    asm volatile(
                        "mma.sync.aligned.m16n8k16.row.col.f32.f16.f16.f32 "
                        "{%0,%1,%2,%3}, {%4,%5,%6,%7}, {%8,%9}, {%0,%1,%2,%3};"
                        : "+f"(acc[0]), "+f"(acc[1]), "+f"(acc[2]), "+f"(acc[3])
                        : "r"(afr[kt + 1][0]), "r"(afr[kt + 1][1]),
                          "r"(afr[kt + 1][2]), "r"(afr[kt + 1][3]),
                          "r"(b[2]), "r"(b[3]));
                    asm volatile(
                        "mma.sync.aligned.m16n8k16.row.col.f32.f16.f16.f32 "
                        "{%0,%1,%2,%3}, {%4,%5,%6,%7}, {%8,%9}, {%0,%1,%2,%3};"
                        : "+f"(acc[4]), "+f"(acc[5]), "+f"(acc[6]), "+f"(acc[7])
                        : "r"(afr[kt + 1][4]), "r"(afr[kt + 1][5]),
                          "r"(afr[kt + 1][6]), "r"(afr[kt + 1][7]),
                          "r"(b[2]), "r"(b[3]));
                }
                float* ob = out + (size_t)t * NELEM + a0 + (nt & 1) * 8 + 2 * thr;
                asm volatile("st.global.cs.v2.f32 [%0], {%1,%2};"
                             :: "l"(ob + (size_t)(h0 + grp) * H),
                                "f"(acc[0]), "f"(acc[1]));
                asm volatile("st.global.cs.v2.f32 [%0], {%1,%2};"
                             :: "l"(ob + (size_t)(h0 + grp + 8) * H),
                                "f"(acc[2]), "f"(acc[3]));
                asm volatile("st.global.cs.v2.f32 [%0], {%1,%2};"
                             :: "l"(ob + (size_t)(h0 + 16 + grp) * H),
                                "f"(acc[4]), "f"(acc[5]));
                asm volatile("st.global.cs.v2.f32 [%0], {%1,%2};"
                             :: "l"(ob + (size_t)(h0 + 24 + grp) * H),
                                "f"(acc[6]), "f"(acc[7]));
            }
        }
    }
}

// ---------------------------------------------------------------------------
// Launch: prep -> scan0 -> combine -> fused(scan+GEMM)
// Output layout: zs_out (T*H*H floats) followed by os (T*H floats).
// ---------------------------------------------------------------------------
extern "C" void kernel_launch(void* const* d_in, const int* in_sizes, int n_in,
                              void* d_out, int out_size) {
    const float* in  = (const float*)d_in[0];   // input_sequence (8192,128)
    const float* lam = (const float*)d_in[1];   // Lambda_bar (128,128)
    const float* Cm  = (const float*)d_in[2];   // C_tilde (128,128)
    const float* wq  = (const float*)d_in[3];   // w_q (3,3)
    const float* Dv  = (const float*)d_in[4];   // D (3,)
    (void)in_sizes; (void)n_in; (void)out_size;

    float* out    = (float*)d_out;
    float* os_out = out + (size_t)TT * NELEM;

    // smem: 2x Zs (halves) + 2x Ys + Xt
    const int fused_smem = 2 * 128 * ZSH * (int)sizeof(__half)
                         + 2 * 8 * 384 * (int)sizeof(float)
                         + LC * 16 * 4 * (int)sizeof(float);
    cudaFuncSetAttribute(fused_kernel, cudaFuncAttributeMaxDynamicSharedMemorySize,
                         fused_smem);

    prep_kernel<<<TT, H>>>(in, wq, Dv, os_out);
    scan0_kernel<<<dim3(8, NC), 256>>>(in, lam);
    combine_kernel<<<NELEM / 256, 256>>>(lam);
    fused_kernel<<<dim3(8, NC), 256, fused_smem>>>(in, lam, Cm, out);
}

// round 11
// speedup vs baseline: 1.0007x; 1.0007x over previous
#include <cuda_runtime.h>
#include <cuda_fp16.h>
#include <cstdint>

// Problem constants (fixed by the dataset)
#define H 128
#define TT 4095          // (8192-3)/2 + 1
#define NC 128           // scan chunks
#define LC 32            // chunk length (last chunk = 31)
#define NELEM (H * H)    // 16384 state elements
#define ZSH 136          // padded Zs row stride in halves (conflict-free)

// Scratch (allocation-free rule: __device__ globals)
static __device__ float g_Y[TT * 3 * H];   // Y[t][w][d] = (w_q @ X_t)[w,d]
static __device__ float g_S[NC * NELEM];   // chunk-local end states
static __device__ float g_cin[NC * NELEM]; // carry-in per chunk

static __device__ __forceinline__ uint32_t smem_u32(const void* p) {
    uint32_t a;
    asm("{ .reg .u64 t; cvta.to.shared.u64 t, %1; cvt.u32.u64 %0, t; }"
        : "=r"(a) : "l"(p));
    return a;
}

// ---------------------------------------------------------------------------
// Kernel 1: Y[t][w][:] = sum_v wq[w][v]*x[2t+v][:], os[t][:] = sum_w D[w]*x[2t+w][:]
// ---------------------------------------------------------------------------
__global__ void prep_kernel(const float* __restrict__ in,
                            const float* __restrict__ wq,
                            const float* __restrict__ Dv,
                            float* __restrict__ os_out) {
    int t = blockIdx.x;
    int d = threadIdx.x;
    float x0 = in[(2 * t + 0) * H + d];
    float x1 = in[(2 * t + 1) * H + d];
    float x2 = in[(2 * t + 2) * H + d];
    g_Y[(t * 3 + 0) * H + d] = wq[0] * x0 + wq[1] * x1 + wq[2] * x2;
    g_Y[(t * 3 + 1) * H + d] = wq[3] * x0 + wq[4] * x1 + wq[5] * x2;
    g_Y[(t * 3 + 2) * H + d] = wq[6] * x0 + wq[7] * x1 + wq[8] * x2;
    os_out[t * H + d] = Dv[0] * x0 + Dv[1] * x1 + Dv[2] * x2;
}

// ---------------------------------------------------------------------------
// Kernel 2: chunk-local scan (zero init), double-buffered Y prefetch,
// Xt triplet layout (one LDS.128 per (tl, a)).
// ---------------------------------------------------------------------------
__global__ __launch_bounds__(256) void scan0_kernel(const float* __restrict__ in,
                                                    const float* __restrict__ Lam) {
    __shared__ float Ys[2][8 * 384];
    __shared__ float Xt[LC * 16 * 4];   // [tl][a_local][w0..w2, pad]

    int c   = blockIdx.y;
    int a0  = blockIdx.x * 16;
    int tid = threadIdx.x;
    int d   = tid & 127;
    int ah  = (tid >> 7) * 8;

    int t0c = c * LC;
    int t1c = t0c + LC; if (t1c > TT) t1c = TT;
    int nb  = (t1c - t0c + 7) >> 3;   // always 4
    int ntl = t1c - t0c;              // valid tl count

    // prologue: prefetch Y(0); stage X triplets for whole chunk
    {
        int nvt0 = t1c - t0c; if (nvt0 > 8) nvt0 = 8;
        uint32_t ydst = smem_u32(Ys[0]);
        const float* ysrc = g_Y + t0c * 384;
        for (int i = tid; i < nvt0 * 96; i += 256)
            asm volatile("cp.async.ca.shared.global [%0], [%1], 16;"
                         :: "r"(ydst + i * 16), "l"(ysrc + i * 4));
        asm volatile("cp.async.commit_group;");
    }
    // Xt layout: 64 slots per tl (16 a x 4). w==3 is padding (zero).
    for (int i = tid; i < ntl * 64; i += 256) {
        int tl = i >> 6, r = i & 63, al = r >> 2, w = r & 3;
        Xt[(tl * 16 + al) * 4 + w] =
            (w < 3) ? in[(size_t)(2 * (t0c + tl) + w) * H + a0 + al] : 0.0f;
    }

    float z[8], lam[8];
#pragma unroll
    for (int k = 0; k < 8; k++) {
        lam[k] = Lam[(a0 + ah + k) * H + d];
        z[k]   = 0.0f;
    }

    for (int e = 0; e < nb; e++) {
        asm volatile("cp.async.wait_group 0;");
        __syncthreads();
        if (e + 1 < nb) {
            int tb1  = t0c + (e + 1) * 8;
            int nvt1 = t1c - tb1; if (nvt1 > 8) nvt1 = 8;
            uint32_t ydst = smem_u32(Ys[(e + 1) & 1]);
            const float* ysrc = g_Y + tb1 * 384;
            for (int i = tid; i < nvt1 * 96; i += 256)
                asm volatile("cp.async.ca.shared.global [%0], [%1], 16;"
                             :: "r"(ydst + i * 16), "l"(ysrc + i * 4));
            asm volatile("cp.async.commit_group;");
        }
        int tb  = t0c + e * 8;
        int nvt = t1c - tb; if (nvt > 8) nvt = 8;
        const float* Yb = Ys[e & 1];
        for (int tl = 0; tl < nvt; tl++) {
            float y0 = Yb[tl * 384 + d];
            float y1 = Yb[tl * 384 + 128 + d];
            float y2 = Yb[tl * 384 + 256 + d];
            int tli = tb - t0c + tl;
#pragma unroll
            for (int k = 0; k < 8; k++) {
                float4 xv = *(const float4*)&Xt[(tli * 16 + ah + k) * 4];
                float u = xv.x * y0 + xv.y * y1 + xv.z * y2;
                z[k] = fmaf(lam[k], z[k], u);
            }
        }
    }

#pragma unroll
    for (int k = 0; k < 8; k++) g_S[c * NELEM + (a0 + ah + k) * H + d] = z[k];
}

// ---------------------------------------------------------------------------
// Kernel 3: sequential carry combine across chunks.
// ---------------------------------------------------------------------------
__global__ void combine_kernel(const float* __restrict__ Lam) {
    int e = blockIdx.x * 256 + threadIdx.x;
    float lam = Lam[e];
    float p = lam;  // lam^32 via 5 squarings
    p = p * p; p = p * p; p = p * p; p = p * p; p = p * p;
    float cin = 0.0f;
    for (int c = 0; c < NC; c++) {
        g_cin[c * NELEM + e] = cin;
        cin = fmaf(p, cin, g_S[c * NELEM + e]);
    }
}

// ---------------------------------------------------------------------------
// Kernel 4: FUSED scan + GEMM (all warps both phases, double-buffered Ys+Zs,
// one barrier per epoch, Y prefetch under previous GEMM).
//
// COLUMN-PERMUTED Zs for coalesced output stores:
//   Even-row-group (rows tl*16+0..7)  row p holds a = {0,1,4,5,8,9,12,13}[p]
//   Odd-row-group  (rows tl*16+8..15) row p holds a = {2,3,6,7,10,11,14,15}[p]
//   => after the (even,odd) mma pair, thread thr holds a = 4*thr..4*thr+3
//      contiguously and writes one st.global.cs.v4 per h-row (64B quads).
//   Scan store remap: row = tl*16 + ((j>>1)&1)*8 + 2*ag + (j&1).
// Numerics identical (pure column permutation); rel_err must stay 2.907e-4.
// ---------------------------------------------------------------------------
__global__ __launch_bounds__(256, 2) void fused_kernel(const float* __restrict__ in,
                                                       const float* __restrict__ Lam,
                                                       const float* __restrict__ Cm,
                                                       float* __restrict__ out) {
    extern __shared__ float smem[];
    __half* ZsA  = (__half*)smem;                 // 128*ZSH halves
    __half* ZsB  = ZsA + 128 * ZSH;
    float*  YsA  = (float*)(ZsB + 128 * ZSH);     // 8*384 floats
    float*  YsB  = YsA + 8 * 384;
    float*  Xt   = YsB + 8 * 384;                 // LC*16*4 floats

    int tid = threadIdx.x;
    int c   = blockIdx.y;
    int a0  = blockIdx.x * 16;
    int wrp = tid >> 5, l = tid & 31;

    int t0c = c * LC;
    int t1c = t0c + LC; if (t1c > TT) t1c = TT;
    int nb  = (t1c - t0c + 7) >> 3;   // always 4
    int ntl = t1c - t0c;

    // scan mapping: 4 a x 2 d
    int d2 = tid & 63;
    int ag = tid >> 6;

    // gemm mapping
    int grp = l >> 2, thr = l & 3;
    int mg  = wrp & 3, ng = wrp >> 2;
    int h0  = mg * 32;
    // ldmatrix lane offset (bytes): row = l&7 (stride ZSH halves), matrix = l>>3
    uint32_t lmoff = (uint32_t)((l & 7) * ZSH * 2 + (l >> 3) * 16);

    // prologue: prefetch Y(0); stage Xt
    {
        int nvt0 = t1c - t0c; if (nvt0 > 8) nvt0 = 8;
        uint32_t ydst = smem_u32(YsA);
        const float* ysrc = g_Y + t0c * 384;
        for (int i = tid; i < nvt0 * 96; i += 256)
            asm volatile("cp.async.ca.shared.global [%0], [%1], 16;"
                         :: "r"(ydst + i * 16), "l"(ysrc + i * 4));
        asm volatile("cp.async.commit_group;");
    }
    // Xt layout: 64 slots per tl (16 a x 4). w==3 is padding (zero).
    for (int i = tid; i < ntl * 64; i += 256) {
        int tl = i >> 6, r = i & 63, al = r >> 2, w = r & 3;
        Xt[(tl * 16 + al) * 4 + w] =
            (w < 3) ? in[(size_t)(2 * (t0c + tl) + w) * H + a0 + al] : 0.0f;
    }

    // A fragments: C rows [h0,h0+32), fp16. 8 k-tiles x 8 half2 regs.
    uint32_t afr[8][8];
#pragma unroll
    for (int kt = 0; kt < 8; kt++) {
        int cb = kt * 16 + 2 * thr;
#pragma unroll
        for (int mt = 0; mt < 2; mt++) {
            const float* r0 = Cm + (h0 + mt * 16 + grp) * H;
            const float* r1 = Cm + (h0 + mt * 16 + grp + 8) * H;
            __half2 p0 = __floats2half2_rn(r0[cb],     r0[cb + 1]);
            __half2 p1 = __floats2half2_rn(r1[cb],     r1[cb + 1]);
            __half2 p2 = __floats2half2_rn(r0[cb + 8], r0[cb + 9]);
            __half2 p3 = __floats2half2_rn(r1[cb + 8], r1[cb + 9]);
            afr[kt][mt * 4 + 0] = *(uint32_t*)&p0;
            afr[kt][mt * 4 + 1] = *(uint32_t*)&p1;
            afr[kt][mt * 4 + 2] = *(uint32_t*)&p2;
            afr[kt][mt * 4 + 3] = *(uint32_t*)&p3;
        }
    }

    // scan state: 4 a x 2 d per thread
    float z[8], lam[8];
#pragma unroll
    for (int j = 0; j < 4; j++) {
        int a = a0 + ag * 4 + j;
        float2 lv = *(const float2*)&Lam[a * H + 2 * d2];
        float2 cv = *(const float2*)&g_cin[c * NELEM + a * H + 2 * d2];
        lam[j * 2]     = lv.x;  lam[j * 2 + 1] = lv.y;
        z[j * 2]       = cv.x;  z[j * 2 + 1]   = cv.y;
    }
    // permuted Zs row offset per j (within a tl block of 16 rows)
    int zrow_j[4];
#pragma unroll
    for (int j = 0; j < 4; j++)
        zrow_j[j] = ((j >> 1) & 1) * 8 + 2 * ag + (j & 1);

    for (int e = 0; e <= nb; e++) {
        asm volatile("cp.async.wait_group 0;");
        __syncthreads();

        if (e < nb) {
            if (e + 1 < nb) {
                int tb1  = t0c + (e + 1) * 8;
                int nvt1 = t1c - tb1; if (nvt1 > 8) nvt1 = 8;
                uint32_t ydst = smem_u32((e + 1) & 1 ? YsB : YsA);
                const float* ysrc = g_Y + tb1 * 384;
                for (int i = tid; i < nvt1 * 96; i += 256)
                    asm volatile("cp.async.ca.shared.global [%0], [%1], 16;"
                                 :: "r"(ydst + i * 16), "l"(ysrc + i * 4));
                asm volatile("cp.async.commit_group;");
            }

            // ---- scan epoch e -> Zs[e&1] (permuted rows) ----
            int tb  = t0c + e * 8;
            int nvt = t1c - tb; if (nvt > 8) nvt = 8;
            const float* Yb = (e & 1) ? YsB : YsA;
            __half* Zb = (e & 1) ? ZsB : ZsA;
            for (int tl = 0; tl < nvt; tl++) {
                float2 y0 = *(const float2*)&Yb[tl * 384 + 2 * d2];
                float2 y1 = *(const float2*)&Yb[tl * 384 + 128 + 2 * d2];
                float2 y2 = *(const float2*)&Yb[tl * 384 + 256 + 2 * d2];
                int tli = tb - t0c + tl;
#pragma unroll
                for (int j = 0; j < 4; j++) {
                    float4 xv = *(const float4*)&Xt[(tli * 16 + ag * 4 + j) * 4];
                    float u0 = xv.x * y0.x + xv.y * y1.x + xv.z * y2.x;
                    float u1 = xv.x * y0.y + xv.y * y1.y + xv.z * y2.y;
                    z[j * 2]     = fmaf(lam[j * 2],     z[j * 2],     u0);
                    z[j * 2 + 1] = fmaf(lam[j * 2 + 1], z[j * 2 + 1], u1);
                    *(__half2*)&Zb[(tl * 16 + zrow_j[j]) * ZSH + 2 * d2] =
                        __floats2half2_rn(z[j * 2], z[j * 2 + 1]);
                }
            }
        }

        // ---- gemm epoch e-1 <- Zs[(e-1)&1] ----
        if (e > 0) {
            int jb = e - 1;
            int tb = t0c + jb * 8;
            const __half* Zb = (jb & 1) ? ZsB : ZsA;
            uint32_t zbase = smem_u32(Zb) + lmoff;
            for (int tl = ng * 4; tl < ng * 4 + 4; tl++) {
                int t = tb + tl;
                if (t >= TT) break;
                float ae[8], ao[8];
#pragma unroll
                for (int i = 0; i < 8; i++) { ae[i] = 0.0f; ao[i] = 0.0f; }
                uint32_t zr_e = zbase + (uint32_t)((tl * 16) * ZSH * 2);
                uint32_t zr_o = zbase + (uint32_t)((tl * 16 + 8) * ZSH * 2);
#pragma unroll
                for (int kp = 0; kp < 4; kp++) {   // 2 kt per ldmatrix.x4
                    uint32_t be[4], bo[4];
                    asm volatile(
                        "ldmatrix.sync.aligned.m8n8.x4.shared.b16 "
                        "{%0,%1,%2,%3}, [%4];"
                        : "=r"(be[0]), "=r"(be[1]), "=r"(be[2]), "=r"(be[3])
                        : "r"(zr_e + (uint32_t)(kp * 64)));
                    asm volatile(
                        "ldmatrix.sync.aligned.m8n8.x4.shared.b16 "
                        "{%0,%1,%2,%3}, [%4];"
                        : "=r"(bo[0]), "=r"(bo[1]), "=r"(bo[2]), "=r"(bo[3])
                        : "r"(zr_o + (uint32_t)(kp * 64)));
                    int kt = kp * 2;
#pragma unroll
                    for (int q = 0; q < 2; q++) {   // kt, kt+1
                        asm volatile(
                            "mma.sync.aligned.m16n8k16.row.col.f32.f16.f16.f32 "
                            "{%0,%1,%2,%3}, {%4,%5,%6,%7}, {%8,%9}, {%0,%1,%2,%3};"
                            : "+f"(ae[0]), "+f"(ae[1]), "+f"(ae[2]), "+f"(ae[3])
                            : "r"(afr[kt + q][0]), "r"(afr[kt + q][1]),
                              "r"(afr[kt + q][2]), "r"(afr[kt + q][3]),
                              "r"(be[q * 2]), "r"(be[q * 2 + 1]));
                        asm volatile(
                            "mma.sync.aligned.m16n8k16.row.col.f32.f16.f16.f32 "
                            "{%0,%1,%2,%3}, {%4,%5,%6,%7}, {%8,%9}, {%0,%1,%2,%3};"
                            : "+f"(ae[4]), "+f"(ae[5]), "+f"(ae[6]), "+f"(ae[7])
                            : "r"(afr[kt + q][4]), "r"(afr[kt + q][5]),
                              "r"(afr[kt + q][6]), "r"(afr[kt + q][7]),
                              "r"(be[q * 2]), "r"(be[q * 2 + 1]));
                        asm volatile(
                            "mma.sync.aligned.m16n8k16.row.col.f32.f16.f16.f32 "
                            "{%0,%1,%2,%3}, {%4,%5,%6,%7}, {%8,%9}, {%0,%1,%2,%3};"
                            : "+f"(ao[0]), "+f"(ao[1]), "+f"(ao[2]), "+f"(ao[3])
                            : "r"(afr[kt + q][0]), "r"(afr[kt + q][1]),
                              "r"(afr[kt + q][2]), "r"(afr[kt + q][3]),
                              "r"(bo[q * 2]), "r"(bo[q * 2 + 1]));
                        asm volatile(
                            "mma.sync.aligned.m16n8k16.row.col.f32.f16.f16.f32 "
                            "{%0,%1,%2,%3}, {%4,%5,%6,%7}, {%8,%9}, {%0,%1,%2,%3};"
                            : "+f"(ao[4]), "+f"(ao[5]), "+f"(ao[6]), "+f"(ao[7])
                            : "r"(afr[kt + q][4]), "r"(afr[kt + q][5]),
                              "r"(afr[kt + q][6]), "r"(afr[kt + q][7]),
                              "r"(bo[q * 2]), "r"(bo[q * 2 + 1]));
                    }
                }
                // coalesced stores: thread thr covers a = 4*thr..4*thr+3
                float* ob = out + (size_t)t * NELEM + a0 + 4 * thr;
                asm volatile("st.global.cs.v4.f32 [%0], {%1,%2,%3,%4};"
                             :: "l"(ob + (size_t)(h0 + grp) * H),
                                "f"(ae[0]), "f"(ae[1]), "f"(ao[0]), "f"(ao[1]));
                asm volatile("st.global.cs.v4.f32 [%0], {%1,%2,%3,%4};"
                             :: "l"(ob + (size_t)(h0 + grp + 8) * H),
                                "f"(ae[2]), "f"(ae[3]), "f"(ao[2]), "f"(ao[3]));
                asm volatile("st.global.cs.v4.f32 [%0], {%1,%2,%3,%4};"
                             :: "l"(ob + (size_t)(h0 + 16 + grp) * H),
                                "f"(ae[4]), "f"(ae[5]), "f"(ao[4]), "f"(ao[5]));
                asm volatile("st.global.cs.v4.f32 [%0], {%1,%2,%3,%4};"
                             :: "l"(ob + (size_t)(h0 + 24 + grp) * H),
                                "f"(ae[6]), "f"(ae[7]), "f"(ao[6]), "f"(ao[7]));
            }
        }
    }
}

// ---------------------------------------------------------------------------
// Launch: prep -> scan0 -> combine -> fused(scan+GEMM)
// Output layout: zs_out (T*H*H floats) followed by os (T*H floats).
// ---------------------------------------------------------------------------
extern "C" void kernel_launch(void* const* d_in, const int* in_sizes, int n_in,
                              void* d_out, int out_size) {
    const float* in  = (const float*)d_in[0];   // input_sequence (8192,128)
    const float* lam = (const float*)d_in[1];   // Lambda_bar (128,128)
    const float* Cm  = (const float*)d_in[2];   // C_tilde (128,128)
    const float* wq  = (const float*)d_in[3];   // w_q (3,3)
    const float* Dv  = (const float*)d_in[4];   // D (3,)
    (void)in_sizes; (void)n_in; (void)out_size;

    float* out    = (float*)d_out;
    float* os_out = out + (size_t)TT * NELEM;

    // smem: 2x Zs (halves) + 2x Ys + Xt
    const int fused_smem = 2 * 128 * ZSH * (int)sizeof(__half)
                         + 2 * 8 * 384 * (int)sizeof(float)
                         + LC * 16 * 4 * (int)sizeof(float);
    cudaFuncSetAttribute(fused_kernel, cudaFuncAttributeMaxDynamicSharedMemorySize,
                         fused_smem);

    prep_kernel<<<TT, H>>>(in, wq, Dv, os_out);
    scan0_kernel<<<dim3(8, NC), 256>>>(in, lam);
    combine_kernel<<<NELEM / 256, 256>>>(lam);
    fused_kernel<<<dim3(8, NC), 256, fused_smem>>>(in, lam, Cm, out);
}

// round 12
// speedup vs baseline: 1.2321x; 1.2312x over previous
#include <cuda_runtime.h>
#include <cuda_fp16.h>
#include <cstdint>

// Problem constants (fixed by the dataset)
#define H 128
#define TT 4095          // (8192-3)/2 + 1
#define NC 128           // scan chunks
#define LC 32            // chunk length (last chunk = 31)
#define NELEM (H * H)    // 16384 state elements
#define ZSH 136          // padded Zs row stride in halves (conflict-free)

// Scratch (allocation-free rule: __device__ globals)
static __device__ float g_Y[TT * 3 * H];   // Y[t][w][d] = (w_q @ X_t)[w,d]
static __device__ float g_S[NC * NELEM];   // chunk-local end states
static __device__ float g_cin[NC * NELEM]; // carry-in per chunk

static __device__ __forceinline__ uint32_t smem_u32(const void* p) {
    uint32_t a;
    asm("{ .reg .u64 t; cvta.to.shared.u64 t, %1; cvt.u32.u64 %0, t; }"
        : "=r"(a) : "l"(p));
    return a;
}

// ---------------------------------------------------------------------------
// Kernel 1: Y[t][w][:] = sum_v wq[w][v]*x[2t+v][:], os[t][:] = sum_w D[w]*x[2t+w][:]
// ---------------------------------------------------------------------------
__global__ void prep_kernel(const float* __restrict__ in,
                            const float* __restrict__ wq,
                            const float* __restrict__ Dv,
                            float* __restrict__ os_out) {
    int t = blockIdx.x;
    int d = threadIdx.x;
    float x0 = in[(2 * t + 0) * H + d];
    float x1 = in[(2 * t + 1) * H + d];
    float x2 = in[(2 * t + 2) * H + d];
    g_Y[(t * 3 + 0) * H + d] = wq[0] * x0 + wq[1] * x1 + wq[2] * x2;
    g_Y[(t * 3 + 1) * H + d] = wq[3] * x0 + wq[4] * x1 + wq[5] * x2;
    g_Y[(t * 3 + 2) * H + d] = wq[6] * x0 + wq[7] * x1 + wq[8] * x2;
    os_out[t * H + d] = Dv[0] * x0 + Dv[1] * x1 + Dv[2] * x2;
}

// ---------------------------------------------------------------------------
// Kernel 2: chunk-local scan (zero init), double-buffered Y prefetch,
// Xt triplet layout (one LDS.128 per (tl, a)).   [R10/R11 proven]
// ---------------------------------------------------------------------------
__global__ __launch_bounds__(256) void scan0_kernel(const float* __restrict__ in,
                                                    const float* __restrict__ Lam) {
    __shared__ float Ys[2][8 * 384];
    __shared__ float Xt[LC * 16 * 4];   // [tl][a_local][w0..w2, pad]

    int c   = blockIdx.y;
    int a0  = blockIdx.x * 16;
    int tid = threadIdx.x;
    int d   = tid & 127;
    int ah  = (tid >> 7) * 8;

    int t0c = c * LC;
    int t1c = t0c + LC; if (t1c > TT) t1c = TT;
    int nb  = (t1c - t0c + 7) >> 3;   // always 4
    int ntl = t1c - t0c;              // valid tl count

    {
        int nvt0 = t1c - t0c; if (nvt0 > 8) nvt0 = 8;
        uint32_t ydst = smem_u32(Ys[0]);
        const float* ysrc = g_Y + t0c * 384;
        for (int i = tid; i < nvt0 * 96; i += 256)
            asm volatile("cp.async.ca.shared.global [%0], [%1], 16;"
                         :: "r"(ydst + i * 16), "l"(ysrc + i * 4));
        asm volatile("cp.async.commit_group;");
    }
    for (int i = tid; i < ntl * 64; i += 256) {
        int tl = i >> 6, r = i & 63, al = r >> 2, w = r & 3;
        Xt[(tl * 16 + al) * 4 + w] =
            (w < 3) ? in[(size_t)(2 * (t0c + tl) + w) * H + a0 + al] : 0.0f;
    }

    float z[8], lam[8];
#pragma unroll
    for (int k = 0; k < 8; k++) {
        lam[k] = Lam[(a0 + ah + k) * H + d];
        z[k]   = 0.0f;
    }

    for (int e = 0; e < nb; e++) {
        asm volatile("cp.async.wait_group 0;");
        __syncthreads();
        if (e + 1 < nb) {
            int tb1  = t0c + (e + 1) * 8;
            int nvt1 = t1c - tb1; if (nvt1 > 8) nvt1 = 8;
            uint32_t ydst = smem_u32(Ys[(e + 1) & 1]);
            const float* ysrc = g_Y + tb1 * 384;
            for (int i = tid; i < nvt1 * 96; i += 256)
                asm volatile("cp.async.ca.shared.global [%0], [%1], 16;"
                             :: "r"(ydst + i * 16), "l"(ysrc + i * 4));
            asm volatile("cp.async.commit_group;");
        }
        int tb  = t0c + e * 8;
        int nvt = t1c - tb; if (nvt > 8) nvt = 8;
        const float* Yb = Ys[e & 1];
        for (int tl = 0; tl < nvt; tl++) {
            float y0 = Yb[tl * 384 + d];
            float y1 = Yb[tl * 384 + 128 + d];
            float y2 = Yb[tl * 384 + 256 + d];
            int tli = tb - t0c + tl;
#pragma unroll
            for (int k = 0; k < 8; k++) {
                float4 xv = *(const float4*)&Xt[(tli * 16 + ah + k) * 4];
                float u = xv.x * y0 + xv.y * y1 + xv.z * y2;
                z[k] = fmaf(lam[k], z[k], u);
            }
        }
    }

#pragma unroll
    for (int k = 0; k < 8; k++) g_S[c * NELEM + (a0 + ah + k) * H + d] = z[k];
}

// ---------------------------------------------------------------------------
// Kernel 3: sequential carry combine across chunks (unroll 4: independent
// loads batched above the dependent fma chain).
// ---------------------------------------------------------------------------
__global__ void combine_kernel(const float* __restrict__ Lam) {
    int e = blockIdx.x * 256 + threadIdx.x;
    float lam = Lam[e];
    float p = lam;  // lam^32 via 5 squarings
    p = p * p; p = p * p; p = p * p; p = p * p; p = p * p;
    float cin = 0.0f;
    for (int c = 0; c < NC; c += 4) {
        float s0 = g_S[(c + 0) * NELEM + e];
        float s1 = g_S[(c + 1) * NELEM + e];
        float s2 = g_S[(c + 2) * NELEM + e];
        float s3 = g_S[(c + 3) * NELEM + e];
        g_cin[(c + 0) * NELEM + e] = cin; cin = fmaf(p, cin, s0);
        g_cin[(c + 1) * NELEM + e] = cin; cin = fmaf(p, cin, s1);
        g_cin[(c + 2) * NELEM + e] = cin; cin = fmaf(p, cin, s2);
        g_cin[(c + 3) * NELEM + e] = cin; cin = fmaf(p, cin, s3);
    }
}

// ---------------------------------------------------------------------------
// Kernel 4: FUSED scan + GEMM, WARP-SPECIALIZED (R6 skeleton + upgrades).
//  Producers (warps 0-3): thread owns 4a x 4d (a = a0+4*wrp+j, d = 4*lane..).
//    Y via 3x LDG.128 from g_Y (L2-resident); X via 3 broadcast LDS.128 from
//    per-chunk packed triplet table Xp; fp16 states -> PERMUTED Zs rows
//    (row = ((j>>1)&1)*8 + 2*wrp + (j&1)) via STS.64.
//  Consumers (warps 4-7): warp = 32 h-rows x full 128-ta panel; C A-frags in
//    regs; ldmatrix.x4 B-frags; e/o parity mma; coalesced st.global.cs.v4.
//  One __syncthreads per batch; producers 1 batch ahead (double-buffered Zs).
// ---------------------------------------------------------------------------
__global__ __launch_bounds__(256, 2) void fused_kernel(const float* __restrict__ in,
                                                       const float* __restrict__ Lam,
                                                       const float* __restrict__ Cm,
                                                       float* __restrict__ out) {
    extern __shared__ float smem[];
    __half* ZsA = (__half*)smem;                 // 128*ZSH halves
    __half* ZsB = ZsA + 128 * ZSH;
    float*  Xp  = (float*)(ZsB + 128 * ZSH);     // LC*4*16 floats (packed triplets)

    int tid = threadIdx.x;
    int c   = blockIdx.y;
    int a0  = blockIdx.x * 16;
    int wrp = tid >> 5, l = tid & 31;

    int t0c = c * LC;
    int t1c = t0c + LC; if (t1c > TT) t1c = TT;
    int nb  = (t1c - t0c + 7) >> 3;   // always 4
    int ntl = t1c - t0c;

    bool producer = (wrp < 4);

    // stage packed X triplets for the whole chunk: Xp[(tl*4+pag)*16 + j*3 + w]
    for (int i = tid; i < ntl * 48; i += 256) {
        int tl = i / 48, r = i % 48, pag = r / 12, idx = r % 12;
        int j = idx / 3, w = idx % 3;
        Xp[(tl * 4 + pag) * 16 + idx] =
            in[(size_t)(2 * (t0c + tl) + w) * H + a0 + pag * 4 + j];
    }

    // ---- producer state ----
    int pd4 = l * 4;            // d base (4 consecutive d)
    int pag = wrp;              // a group: a = a0 + 4*pag + j
    float z[16], lam[16];
    int prow[4];
    if (producer) {
#pragma unroll
        for (int j = 0; j < 4; j++) {
            int a = a0 + pag * 4 + j;
            float4 lv = *(const float4*)&Lam[a * H + pd4];
            float4 cv = *(const float4*)&g_cin[c * NELEM + a * H + pd4];
            lam[j * 4 + 0] = lv.x; lam[j * 4 + 1] = lv.y;
            lam[j * 4 + 2] = lv.z; lam[j * 4 + 3] = lv.w;
            z[j * 4 + 0] = cv.x; z[j * 4 + 1] = cv.y;
            z[j * 4 + 2] = cv.z; z[j * 4 + 3] = cv.w;
            prow[j] = ((j >> 1) & 1) * 8 + 2 * pag + (j & 1);
        }
    }

    // ---- consumer state: A fragments (C rows [h0,h0+32), fp16) ----
    int grp = l >> 2, thr = l & 3;
    int mg  = wrp - 4;          // 0..3
    int h0  = mg * 32;
    uint32_t lmoff = (uint32_t)((l & 7) * ZSH * 2 + (l >> 3) * 16);
    uint32_t afr[8][8];
    if (!producer) {
#pragma unroll
        for (int kt = 0; kt < 8; kt++) {
            int cb = kt * 16 + 2 * thr;
#pragma unroll
            for (int mt = 0; mt < 2; mt++) {
                const float* r0 = Cm + (h0 + mt * 16 + grp) * H;
                const float* r1 = Cm + (h0 + mt * 16 + grp + 8) * H;
                __half2 p0 = __floats2half2_rn(r0[cb],     r0[cb + 1]);
                __half2 p1 = __floats2half2_rn(r1[cb],     r1[cb + 1]);
                __half2 p2 = __floats2half2_rn(r0[cb + 8], r0[cb + 9]);
                __half2 p3 = __floats2half2_rn(r1[cb + 8], r1[cb + 9]);
                afr[kt][mt * 4 + 0] = *(uint32_t*)&p0;
                afr[kt][mt * 4 + 1] = *(uint32_t*)&p1;
                afr[kt][mt * 4 + 2] = *(uint32_t*)&p2;
                afr[kt][mt * 4 + 3] = *(uint32_t*)&p3;
            }
        }
    }
    __syncthreads();   // Xp staged

    for (int ib = 0; ib <= nb; ib++) {
        if (producer && ib < nb) {
            int tb  = t0c + ib * 8;
            int nvt = t1c - tb; if (nvt > 8) nvt = 8;
            __half* Zb = (ib & 1) ? ZsB : ZsA;
            for (int tl = 0; tl < nvt; tl++) {
                int t = tb + tl;
                const float* yb = g_Y + t * 384;
                float4 y0 = *(const float4*)(yb + pd4);
                float4 y1 = *(const float4*)(yb + 128 + pd4);
                float4 y2 = *(const float4*)(yb + 256 + pd4);
                const float* xb = &Xp[((tb - t0c + tl) * 4 + pag) * 16];
                float4 f0 = *(const float4*)(xb);
                float4 f1 = *(const float4*)(xb + 4);
                float4 f2 = *(const float4*)(xb + 8);
                float xw[4][3] = {{f0.x, f0.y, f0.z}, {f0.w, f1.x, f1.y},
                                  {f1.z, f1.w, f2.x}, {f2.y, f2.z, f2.w}};
#pragma unroll
                for (int j = 0; j < 4; j++) {
                    float xa = xw[j][0], xm = xw[j][1], xc = xw[j][2];
                    float u0 = xa * y0.x + xm * y1.x + xc * y2.x;
                    float u1 = xa * y0.y + xm * y1.y + xc * y2.y;
                    float u2 = xa * y0.z + xm * y1.z + xc * y2.z;
                    float u3 = xa * y0.w + xm * y1.w + xc * y2.w;
                    z[j * 4 + 0] = fmaf(lam[j * 4 + 0], z[j * 4 + 0], u0);
                    z[j * 4 + 1] = fmaf(lam[j * 4 + 1], z[j * 4 + 1], u1);
                    z[j * 4 + 2] = fmaf(lam[j * 4 + 2], z[j * 4 + 2], u2);
                    z[j * 4 + 3] = fmaf(lam[j * 4 + 3], z[j * 4 + 3], u3);
                    __half2 p0 = __floats2half2_rn(z[j * 4 + 0], z[j * 4 + 1]);
                    __half2 p1 = __floats2half2_rn(z[j * 4 + 2], z[j * 4 + 3]);
                    uint2 pk;
                    pk.x = *(uint32_t*)&p0;
                    pk.y = *(uint32_t*)&p1;
                    *(uint2*)&Zb[(tl * 16 + prow[j]) * ZSH + pd4] = pk;
                }
            }
        } else if (!producer && ib > 0) {
            int jb = ib - 1;
            int tb = t0c + jb * 8;
            const __half* Zb = (jb & 1) ? ZsB : ZsA;
            uint32_t zbase = smem_u32(Zb) + lmoff;
            for (int tl = 0; tl < 8; tl++) {
                int t = tb + tl;
                if (t >= TT) break;
                float ae[8], ao[8];
#pragma unroll
                for (int i = 0; i < 8; i++) { ae[i] = 0.0f; ao[i] = 0.0f; }
                uint32_t zr_e = zbase + (uint32_t)((tl * 16) * ZSH * 2);
                uint32_t zr_o = zbase + (uint32_t)((tl * 16 + 8) * ZSH * 2);
#pragma unroll
                for (int kp = 0; kp < 4; kp++) {
                    uint32_t be[4], bo[4];
                    asm volatile(
                        "ldmatrix.sync.aligned.m8n8.x4.shared.b16 "
                        "{%0,%1,%2,%3}, [%4];"
                        : "=r"(be[0]), "=r"(be[1]), "=r"(be[2]), "=r"(be[3])
                        : "r"(zr_e + (uint32_t)(kp * 64)));
                    asm volatile(
                        "ldmatrix.sync.aligned.m8n8.x4.shared.b16 "
                        "{%0,%1,%2,%3}, [%4];"
                        : "=r"(bo[0]), "=r"(bo[1]), "=r"(bo[2]), "=r"(bo[3])
                        : "r"(zr_o + (uint32_t)(kp * 64)));
                    int kt = kp * 2;
#pragma unroll
                    for (int q = 0; q < 2; q++) {
                        asm volatile(
                            "mma.sync.aligned.m16n8k16.row.col.f32.f16.f16.f32 "
                            "{%0,%1,%2,%3}, {%4,%5,%6,%7}, {%8,%9}, {%0,%1,%2,%3};"
                            : "+f"(ae[0]), "+f"(ae[1]), "+f"(ae[2]), "+f"(ae[3])
                            : "r"(afr[kt + q][0]), "r"(afr[kt + q][1]),
                              "r"(afr[kt + q][2]), "r"(afr[kt + q][3]),
                              "r"(be[q * 2]), "r"(be[q * 2 + 1]));
                        asm volatile(
                            "mma.sync.aligned.m16n8k16.row.col.f32.f16.f16.f32 "
                            "{%0,%1,%2,%3}, {%4,%5,%6,%7}, {%8,%9}, {%0,%1,%2,%3};"
                            : "+f"(ae[4]), "+f"(ae[5]), "+f"(ae[6]), "+f"(ae[7])
                            : "r"(afr[kt + q][4]), "r"(afr[kt + q][5]),
                              "r"(afr[kt + q][6]), "r"(afr[kt + q][7]),
                              "r"(be[q * 2]), "r"(be[q * 2 + 1]));
                        asm volatile(
                            "mma.sync.aligned.m16n8k16.row.col.f32.f16.f16.f32 "
                            "{%0,%1,%2,%3}, {%4,%5,%6,%7}, {%8,%9}, {%0,%1,%2,%3};"
                            : "+f"(ao[0]), "+f"(ao[1]), "+f"(ao[2]), "+f"(ao[3])
                            : "r"(afr[kt + q][0]), "r"(afr[kt + q][1]),
                              "r"(afr[kt + q][2]), "r"(afr[kt + q][3]),
                              "r"(bo[q * 2]), "r"(bo[q * 2 + 1]));
                        asm volatile(
                            "mma.sync.aligned.m16n8k16.row.col.f32.f16.f16.f32 "
                            "{%0,%1,%2,%3}, {%4,%5,%6,%7}, {%8,%9}, {%0,%1,%2,%3};"
                            : "+f"(ao[4]), "+f"(ao[5]), "+f"(ao[6]), "+f"(ao[7])
                            : "r"(afr[kt + q][4]), "r"(afr[kt + q][5]),
                              "r"(afr[kt + q][6]), "r"(afr[kt + q][7]),
                              "r"(bo[q * 2]), "r"(bo[q * 2 + 1]));
                    }
                }
                float* ob = out + (size_t)t * NELEM + a0 + 4 * thr;
                asm volatile("st.global.cs.v4.f32 [%0], {%1,%2,%3,%4};"
                             :: "l"(ob + (size_t)(h0 + grp) * H),
                                "f"(ae[0]), "f"(ae[1]), "f"(ao[0]), "f"(ao[1]));
                asm volatile("st.global.cs.v4.f32 [%0], {%1,%2,%3,%4};"
                             :: "l"(ob + (size_t)(h0 + grp + 8) * H),
                                "f"(ae[2]), "f"(ae[3]), "f"(ao[2]), "f"(ao[3]));
                asm volatile("st.global.cs.v4.f32 [%0], {%1,%2,%3,%4};"
                             :: "l"(ob + (size_t)(h0 + 16 + grp) * H),
                                "f"(ae[4]), "f"(ae[5]), "f"(ao[4]), "f"(ao[5]));
                asm volatile("st.global.cs.v4.f32 [%0], {%1,%2,%3,%4};"
                             :: "l"(ob + (size_t)(h0 + 24 + grp) * H),
                                "f"(ae[6]), "f"(ae[7]), "f"(ao[6]), "f"(ao[7]));
            }
        }
        __syncthreads();
    }
}

// ---------------------------------------------------------------------------
// Launch: prep -> scan0 -> combine -> fused(scan+GEMM, warp-specialized)
// Output layout: zs_out (T*H*H floats) followed by os (T*H floats).
// ---------------------------------------------------------------------------
extern "C" void kernel_launch(void* const* d_in, const int* in_sizes, int n_in,
                              void* d_out, int out_size) {
    const float* in  = (const float*)d_in[0];   // input_sequence (8192,128)
    const float* lam = (const float*)d_in[1];   // Lambda_bar (128,128)
    const float* Cm  = (const float*)d_in[2];   // C_tilde (128,128)
    const float* wq  = (const float*)d_in[3];   // w_q (3,3)
    const float* Dv  = (const float*)d_in[4];   // D (3,)
    (void)in_sizes; (void)n_in; (void)out_size;

    float* out    = (float*)d_out;
    float* os_out = out + (size_t)TT * NELEM;

    // smem: 2x Zs (halves) + packed Xp
    const int fused_smem = 2 * 128 * ZSH * (int)sizeof(__half)
                         + LC * 4 * 16 * (int)sizeof(float);
    cudaFuncSetAttribute(fused_kernel, cudaFuncAttributeMaxDynamicSharedMemorySize,
                         fused_smem);

    prep_kernel<<<TT, H>>>(in, wq, Dv, os_out);
    scan0_kernel<<<dim3(8, NC), 256>>>(in, lam);
    combine_kernel<<<NELEM / 256, 256>>>(lam);
    fused_kernel<<<dim3(8, NC), 256, fused_smem>>>(in, lam, Cm, out);
}

// round 13
// speedup vs baseline: 1.3853x; 1.1243x over previous
#include <cuda_runtime.h>
#include <cuda_fp16.h>
#include <cstdint>

// Problem constants (fixed by the dataset)
#define H 128
#define TT 4095          // (8192-3)/2 + 1
#define NC 128           // scan chunks
#define LC 32            // chunk length (last chunk = 31)
#define NELEM (H * H)    // 16384 state elements
#define ZSH 136          // padded Zs row stride in halves (conflict-free)
#define CPC 4            // chunks per persistent CTA
#define XRS 1072         // Xr buffer floats (67 rows x 16)

// Scratch (allocation-free rule: __device__ globals)
static __device__ float g_Y[TT * 3 * H];   // Y[t][w][d] = (w_q @ X_t)[w,d]
static __device__ float g_S[NC * NELEM];   // chunk-local end states
static __device__ float g_cin[NC * NELEM]; // carry-in per chunk

static __device__ __forceinline__ uint32_t smem_u32(const void* p) {
    uint32_t a;
    asm("{ .reg .u64 t; cvta.to.shared.u64 t, %1; cvt.u32.u64 %0, t; }"
        : "=r"(a) : "l"(p));
    return a;
}

// ---------------------------------------------------------------------------
// Kernel 1: Y[t][w][:] = sum_v wq[w][v]*x[2t+v][:], os[t][:] = sum_w D[w]*x[2t+w][:]
// ---------------------------------------------------------------------------
__global__ void prep_kernel(const float* __restrict__ in,
                            const float* __restrict__ wq,
                            const float* __restrict__ Dv,
                            float* __restrict__ os_out) {
    int t = blockIdx.x;
    int d = threadIdx.x;
    float x0 = in[(2 * t + 0) * H + d];
    float x1 = in[(2 * t + 1) * H + d];
    float x2 = in[(2 * t + 2) * H + d];
    g_Y[(t * 3 + 0) * H + d] = wq[0] * x0 + wq[1] * x1 + wq[2] * x2;
    g_Y[(t * 3 + 1) * H + d] = wq[3] * x0 + wq[4] * x1 + wq[5] * x2;
    g_Y[(t * 3 + 2) * H + d] = wq[6] * x0 + wq[7] * x1 + wq[8] * x2;
    os_out[t * H + d] = Dv[0] * x0 + Dv[1] * x1 + Dv[2] * x2;
}

// ---------------------------------------------------------------------------
// Kernel 2: chunk-local scan (zero init), double-buffered Y prefetch,
// Xt triplet layout.   [R12 proven]
// ---------------------------------------------------------------------------
__global__ __launch_bounds__(256) void scan0_kernel(const float* __restrict__ in,
                                                    const float* __restrict__ Lam) {
    __shared__ float Ys[2][8 * 384];
    __shared__ float Xt[LC * 16 * 4];

    int c   = blockIdx.y;
    int a0  = blockIdx.x * 16;
    int tid = threadIdx.x;
    int d   = tid & 127;
    int ah  = (tid >> 7) * 8;

    int t0c = c * LC;
    int t1c = t0c + LC; if (t1c > TT) t1c = TT;
    int nb  = (t1c - t0c + 7) >> 3;
    int ntl = t1c - t0c;

    {
        int nvt0 = t1c - t0c; if (nvt0 > 8) nvt0 = 8;
        uint32_t ydst = smem_u32(Ys[0]);
        const float* ysrc = g_Y + t0c * 384;
        for (int i = tid; i < nvt0 * 96; i += 256)
            asm volatile("cp.async.ca.shared.global [%0], [%1], 16;"
                         :: "r"(ydst + i * 16), "l"(ysrc + i * 4));
        asm volatile("cp.async.commit_group;");
    }
    for (int i = tid; i < ntl * 64; i += 256) {
        int tl = i >> 6, r = i & 63, al = r >> 2, w = r & 3;
        Xt[(tl * 16 + al) * 4 + w] =
            (w < 3) ? in[(size_t)(2 * (t0c + tl) + w) * H + a0 + al] : 0.0f;
    }

    float z[8], lam[8];
#pragma unroll
    for (int k = 0; k < 8; k++) {
        lam[k] = Lam[(a0 + ah + k) * H + d];
        z[k]   = 0.0f;
    }

    for (int e = 0; e < nb; e++) {
        asm volatile("cp.async.wait_group 0;");
        __syncthreads();
        if (e + 1 < nb) {
            int tb1  = t0c + (e + 1) * 8;
            int nvt1 = t1c - tb1; if (nvt1 > 8) nvt1 = 8;
            uint32_t ydst = smem_u32(Ys[(e + 1) & 1]);
            const float* ysrc = g_Y + tb1 * 384;
            for (int i = tid; i < nvt1 * 96; i += 256)
                asm volatile("cp.async.ca.shared.global [%0], [%1], 16;"
                             :: "r"(ydst + i * 16), "l"(ysrc + i * 4));
            asm volatile("cp.async.commit_group;");
        }
        int tb  = t0c + e * 8;
        int nvt = t1c - tb; if (nvt > 8) nvt = 8;
        const float* Yb = Ys[e & 1];
        for (int tl = 0; tl < nvt; tl++) {
            float y0 = Yb[tl * 384 + d];
            float y1 = Yb[tl * 384 + 128 + d];
            float y2 = Yb[tl * 384 + 256 + d];
            int tli = tb - t0c + tl;
#pragma unroll
            for (int k = 0; k < 8; k++) {
                float4 xv = *(const float4*)&Xt[(tli * 16 + ah + k) * 4];
                float u = xv.x * y0 + xv.y * y1 + xv.z * y2;
                z[k] = fmaf(lam[k], z[k], u);
            }
        }
    }

#pragma unroll
    for (int k = 0; k < 8; k++) g_S[c * NELEM + (a0 + ah + k) * H + d] = z[k];
}

// ---------------------------------------------------------------------------
// Kernel 3: sequential carry combine across chunks (unroll 4).
// ---------------------------------------------------------------------------
__global__ void combine_kernel(const float* __restrict__ Lam) {
    int e = blockIdx.x * 256 + threadIdx.x;
    float lam = Lam[e];
    float p = lam;  // lam^32 via 5 squarings
    p = p * p; p = p * p; p = p * p; p = p * p; p = p * p;
    float cin = 0.0f;
    for (int c = 0; c < NC; c += 4) {
        float s0 = g_S[(c + 0) * NELEM + e];
        float s1 = g_S[(c + 1) * NELEM + e];
        float s2 = g_S[(c + 2) * NELEM + e];
        float s3 = g_S[(c + 3) * NELEM + e];
        g_cin[(c + 0) * NELEM + e] = cin; cin = fmaf(p, cin, s0);
        g_cin[(c + 1) * NELEM + e] = cin; cin = fmaf(p, cin, s1);
        g_cin[(c + 2) * NELEM + e] = cin; cin = fmaf(p, cin, s2);
        g_cin[(c + 3) * NELEM + e] = cin; cin = fmaf(p, cin, s3);
    }
}

// ---------------------------------------------------------------------------
// Kernel 4: FUSED scan + GEMM, WARP-SPECIALIZED, PERSISTENT single-wave CTAs.
//  Grid (8, 32): CTA owns a-tile ax and 4 consecutive chunks (16 batches) as
//  ONE pipeline: epoch bi scans batch bi (t = cy*128 + bi*8 + tl) into
//  Zs[bi&1]; consumers gemm batch bi-1. Producers reload carry-in from g_cin
//  at chunk boundaries. Y(bi+1) and (at chunk edges) X rows prefetched each
//  epoch via ONE cp.async commit group -> zero exposed latency in the scan.
// ---------------------------------------------------------------------------
__global__ __launch_bounds__(256, 2) void fused_kernel(const float* __restrict__ in,
                                                       const float* __restrict__ Lam,
                                                       const float* __restrict__ Cm,
                                                       float* __restrict__ out) {
    extern __shared__ float smem[];
    __half* ZsA = (__half*)smem;                 // 128*ZSH halves
    __half* ZsB = ZsA + 128 * ZSH;
    float*  Ys0 = (float*)(ZsB + 128 * ZSH);     // 8*384 floats
    float*  Ys1 = Ys0 + 8 * 384;
    float*  Xr  = Ys1 + 8 * 384;                 // 2 * XRS floats (raw x rows)

    int tid = threadIdx.x;
    int cy  = blockIdx.y;                        // 4-chunk group
    int a0  = blockIdx.x * 16;
    int wrp = tid >> 5, l = tid & 31;

    bool producer = (wrp < 4);
    int Tbase = cy * 128;                        // first t of this CTA

    // ---- producer state ----
    int pd4 = l * 4;
    int pag = wrp;
    float z[16], lam[16];
    int prow[4];
    if (producer) {
#pragma unroll
        for (int j = 0; j < 4; j++) {
            int a = a0 + pag * 4 + j;
            float4 lv = *(const float4*)&Lam[a * H + pd4];
            lam[j * 4 + 0] = lv.x; lam[j * 4 + 1] = lv.y;
            lam[j * 4 + 2] = lv.z; lam[j * 4 + 3] = lv.w;
            prow[j] = ((j >> 1) & 1) * 8 + 2 * pag + (j & 1);
        }
        // prologue prefetch: Y(0) + Xr(chunk 0), one commit group
        {
            int nvt0 = TT - Tbase; if (nvt0 > 8) nvt0 = 8;
            uint32_t ydst = smem_u32(Ys0);
            const float* ysrc = g_Y + (size_t)Tbase * 384;
            for (int i = tid; i < nvt0 * 96; i += 128)
                asm volatile("cp.async.ca.shared.global [%0], [%1], 16;"
                             :: "r"(ydst + i * 16), "l"(ysrc + i * 4));
            uint32_t xdst = smem_u32(Xr);
            for (int i = tid; i < 67 * 4; i += 128) {
                int r = i >> 2, q = i & 3;
                int row = 2 * Tbase + r;
                if (row < 8192)
                    asm volatile("cp.async.ca.shared.global [%0], [%1], 16;"
                                 :: "r"(xdst + (r * 16 + q * 4) * 4),
                                    "l"(in + (size_t)row * H + a0 + q * 4));
            }
            asm volatile("cp.async.commit_group;");
        }
    }

    // ---- consumer state: A fragments (C rows [h0,h0+32), fp16) ----
    int grp = l >> 2, thr = l & 3;
    int mg  = wrp - 4;
    int h0  = mg * 32;
    uint32_t lmoff = (uint32_t)((l & 7) * ZSH * 2 + (l >> 3) * 16);
    uint32_t afr[8][8];
    if (!producer) {
#pragma unroll
        for (int kt = 0; kt < 8; kt++) {
            int cb = kt * 16 + 2 * thr;
#pragma unroll
            for (int mt = 0; mt < 2; mt++) {
                const float* r0 = Cm + (h0 + mt * 16 + grp) * H;
                const float* r1 = Cm + (h0 + mt * 16 + grp + 8) * H;
                __half2 p0 = __floats2half2_rn(r0[cb],     r0[cb + 1]);
                __half2 p1 = __floats2half2_rn(r1[cb],     r1[cb + 1]);
                __half2 p2 = __floats2half2_rn(r0[cb + 8], r0[cb + 9]);
                __half2 p3 = __floats2half2_rn(r1[cb + 8], r1[cb + 9]);
                afr[kt][mt * 4 + 0] = *(uint32_t*)&p0;
                afr[kt][mt * 4 + 1] = *(uint32_t*)&p1;
                afr[kt][mt * 4 + 2] = *(uint32_t*)&p2;
                afr[kt][mt * 4 + 3] = *(uint32_t*)&p3;
            }
        }
    }

    const int NB = 4 * CPC;   // 16 batches per CTA

    for (int bi = 0; bi <= NB; bi++) {
        asm volatile("cp.async.wait_group 0;");
        __syncthreads();

        if (producer && bi < NB) {
            int tb = Tbase + bi * 8;

            // prefetch Y(bi+1) (+ Xr of next chunk at chunk edge), one group
            if (bi + 1 < NB) {
                int tb1  = tb + 8;
                int nvt1 = TT - tb1; if (nvt1 > 8) nvt1 = 8;
                uint32_t ydst = smem_u32(((bi + 1) & 1) ? Ys1 : Ys0);
                const float* ysrc = g_Y + (size_t)tb1 * 384;
                for (int i = tid; i < nvt1 * 96; i += 128)
                    asm volatile("cp.async.ca.shared.global [%0], [%1], 16;"
                                 :: "r"(ydst + i * 16), "l"(ysrc + i * 4));
                if ((bi & 3) == 3) {
                    int ck1  = (bi >> 2) + 1;
                    int t0c1 = Tbase + ck1 * 32;
                    uint32_t xdst = smem_u32(Xr + (ck1 & 1) * XRS);
                    for (int i = tid; i < 67 * 4; i += 128) {
                        int r = i >> 2, q = i & 3;
                        int row = 2 * t0c1 + r;
                        if (row < 8192)
                            asm volatile("cp.async.ca.shared.global [%0], [%1], 16;"
                                         :: "r"(xdst + (r * 16 + q * 4) * 4),
                                            "l"(in + (size_t)row * H + a0 + q * 4));
                    }
                }
                asm volatile("cp.async.commit_group;");
            }

            // chunk start: reload carry-in
            if ((bi & 3) == 0) {
                int gc = cy * CPC + (bi >> 2);
#pragma unroll
                for (int j = 0; j < 4; j++) {
                    int a = a0 + pag * 4 + j;
                    float4 cv = *(const float4*)&g_cin[gc * NELEM + a * H + pd4];
                    z[j * 4 + 0] = cv.x; z[j * 4 + 1] = cv.y;
                    z[j * 4 + 2] = cv.z; z[j * 4 + 3] = cv.w;
                }
            }

            // ---- scan batch bi -> Zs[bi&1] ----
            int nvt = TT - tb; if (nvt > 8) nvt = 8;
            const float* Yb = (bi & 1) ? Ys1 : Ys0;
            const float* Xb = Xr + ((bi >> 2) & 1) * XRS;
            __half* Zb = (bi & 1) ? ZsB : ZsA;
            int lb = (bi & 3) * 8;    // batch offset within chunk (t-steps)
            for (int tl = 0; tl < nvt; tl++) {
                float4 y0 = *(const float4*)&Yb[tl * 384 + pd4];
                float4 y1 = *(const float4*)&Yb[tl * 384 + 128 + pd4];
                float4 y2 = *(const float4*)&Yb[tl * 384 + 256 + pd4];
                int lr = 2 * (lb + tl);
                float4 x0 = *(const float4*)&Xb[(lr + 0) * 16 + pag * 4];
                float4 x1 = *(const float4*)&Xb[(lr + 1) * 16 + pag * 4];
                float4 x2 = *(const float4*)&Xb[(lr + 2) * 16 + pag * 4];
                float xw[4][3] = {{x0.x, x1.x, x2.x}, {x0.y, x1.y, x2.y},
                                  {x0.z, x1.z, x2.z}, {x0.w, x1.w, x2.w}};
#pragma unroll
                for (int j = 0; j < 4; j++) {
                    float xa = xw[j][0], xm = xw[j][1], xc = xw[j][2];
                    float u0 = xa * y0.x + xm * y1.x + xc * y2.x;
                    float u1 = xa * y0.y + xm * y1.y + xc * y2.y;
                    float u2 = xa * y0.z + xm * y1.z + xc * y2.z;
                    float u3 = xa * y0.w + xm * y1.w + xc * y2.w;
                    z[j * 4 + 0] = fmaf(lam[j * 4 + 0], z[j * 4 + 0], u0);
                    z[j * 4 + 1] = fmaf(lam[j * 4 + 1], z[j * 4 + 1], u1);
                    z[j * 4 + 2] = fmaf(lam[j * 4 + 2], z[j * 4 + 2], u2);
                    z[j * 4 + 3] = fmaf(lam[j * 4 + 3], z[j * 4 + 3], u3);
                    __half2 p0 = __floats2half2_rn(z[j * 4 + 0], z[j * 4 + 1]);
                    __half2 p1 = __floats2half2_rn(z[j * 4 + 2], z[j * 4 + 3]);
                    uint2 pk;
                    pk.x = *(uint32_t*)&p0;
                    pk.y = *(uint32_t*)&p1;
                    *(uint2*)&Zb[(tl * 16 + prow[j]) * ZSH + pd4] = pk;
                }
            }
        } else if (!producer && bi > 0) {
            int tb = Tbase + (bi - 1) * 8;
            const __half* Zb = ((bi - 1) & 1) ? ZsB : ZsA;
            uint32_t zbase = smem_u32(Zb) + lmoff;
            for (int tl = 0; tl < 8; tl++) {
                int t = tb + tl;
                if (t >= TT) break;
                float ae[8], ao[8];
#pragma unroll
                for (int i = 0; i < 8; i++) { ae[i] = 0.0f; ao[i] = 0.0f; }
                uint32_t zr_e = zbase + (uint32_t)((tl * 16) * ZSH * 2);
                uint32_t zr_o = zbase + (uint32_t)((tl * 16 + 8) * ZSH * 2);
#pragma unroll
                for (int kp = 0; kp < 4; kp++) {
                    uint32_t be[4], bo[4];
                    asm volatile(
                        "ldmatrix.sync.aligned.m8n8.x4.shared.b16 "
                        "{%0,%1,%2,%3}, [%4];"
                        : "=r"(be[0]), "=r"(be[1]), "=r"(be[2]), "=r"(be[3])
                        : "r"(zr_e + (uint32_t)(kp * 64)));
                    asm volatile(
                        "ldmatrix.sync.aligned.m8n8.x4.shared.b16 "
                        "{%0,%1,%2,%3}, [%4];"
                        : "=r"(bo[0]), "=r"(bo[1]), "=r"(bo[2]), "=r"(bo[3])
                        : "r"(zr_o + (uint32_t)(kp * 64)));
                    int kt = kp * 2;
#pragma unroll
                    for (int q = 0; q < 2; q++) {
                        asm volatile(
                            "mma.sync.aligned.m16n8k16.row.col.f32.f16.f16.f32 "
                            "{%0,%1,%2,%3}, {%4,%5,%6,%7}, {%8,%9}, {%0,%1,%2,%3};"
                            : "+f"(ae[0]), "+f"(ae[1]), "+f"(ae[2]), "+f"(ae[3])
                            : "r"(afr[kt + q][0]), "r"(afr[kt + q][1]),
                              "r"(afr[kt + q][2]), "r"(afr[kt + q][3]),
                              "r"(be[q * 2]), "r"(be[q * 2 + 1]));
                        asm volatile(
                            "mma.sync.aligned.m16n8k16.row.col.f32.f16.f16.f32 "
                            "{%0,%1,%2,%3}, {%4,%5,%6,%7}, {%8,%9}, {%0,%1,%2,%3};"
                            : "+f"(ae[4]), "+f"(ae[5]), "+f"(ae[6]), "+f"(ae[7])
                            : "r"(afr[kt + q][4]), "r"(afr[kt + q][5]),
                              "r"(afr[kt + q][6]), "r"(afr[kt + q][7]),
                              "r"(be[q * 2]), "r"(be[q * 2 + 1]));
                        asm volatile(
                            "mma.sync.aligned.m16n8k16.row.col.f32.f16.f16.f32 "
                            "{%0,%1,%2,%3}, {%4,%5,%6,%7}, {%8,%9}, {%0,%1,%2,%3};"
                            : "+f"(ao[0]), "+f"(ao[1]), "+f"(ao[2]), "+f"(ao[3])
                            : "r"(afr[kt + q][0]), "r"(afr[kt + q][1]),
                              "r"(afr[kt + q][2]), "r"(afr[kt + q][3]),
                              "r"(bo[q * 2]), "r"(bo[q * 2 + 1]));
                        asm volatile(
                            "mma.sync.aligned.m16n8k16.row.col.f32.f16.f16.f32 "
                            "{%0,%1,%2,%3}, {%4,%5,%6,%7}, {%8,%9}, {%0,%1,%2,%3};"
                            : "+f"(ao[4]), "+f"(ao[5]), "+f"(ao[6]), "+f"(ao[7])
                            : "r"(afr[kt + q][4]), "r"(afr[kt + q][5]),
                              "r"(afr[kt + q][6]), "r"(afr[kt + q][7]),
                              "r"(bo[q * 2]), "r"(bo[q * 2 + 1]));
                    }
                }
                float* ob = out + (size_t)t * NELEM + a0 + 4 * thr;
                asm volatile("st.global.cs.v4.f32 [%0], {%1,%2,%3,%4};"
                             :: "l"(ob + (size_t)(h0 + grp) * H),
                                "f"(ae[0]), "f"(ae[1]), "f"(ao[0]), "f"(ao[1]));
                asm volatile("st.global.cs.v4.f32 [%0], {%1,%2,%3,%4};"
                             :: "l"(ob + (size_t)(h0 + grp + 8) * H),
                                "f"(ae[2]), "f"(ae[3]), "f"(ao[2]), "f"(ao[3]));
                asm volatile("st.global.cs.v4.f32 [%0], {%1,%2,%3,%4};"
                             :: "l"(ob + (size_t)(h0 + 16 + grp) * H),
                                "f"(ae[4]), "f"(ae[5]), "f"(ao[4]), "f"(ao[5]));
                asm volatile("st.global.cs.v4.f32 [%0], {%1,%2,%3,%4};"
                             :: "l"(ob + (size_t)(h0 + 24 + grp) * H),
                                "f"(ae[6]), "f"(ae[7]), "f"(ao[6]), "f"(ao[7]));
            }
        }
        __syncthreads();
    }
}

// ---------------------------------------------------------------------------
// Launch: prep -> scan0 -> combine -> fused(persistent warp-specialized)
// Output layout: zs_out (T*H*H floats) followed by os (T*H floats).
// ---------------------------------------------------------------------------
extern "C" void kernel_launch(void* const* d_in, const int* in_sizes, int n_in,
                              void* d_out, int out_size) {
    const float* in  = (const float*)d_in[0];   // input_sequence (8192,128)
    const float* lam = (const float*)d_in[1];   // Lambda_bar (128,128)
    const float* Cm  = (const float*)d_in[2];   // C_tilde (128,128)
    const float* wq  = (const float*)d_in[3];   // w_q (3,3)
    const float* Dv  = (const float*)d_in[4];   // D (3,)
    (void)in_sizes; (void)n_in; (void)out_size;

    float* out    = (float*)d_out;
    float* os_out = out + (size_t)TT * NELEM;

    // smem: 2x Zs (halves) + 2x Ys + 2x Xr
    const int fused_smem = 2 * 128 * ZSH * (int)sizeof(__half)
                         + 2 * 8 * 384 * (int)sizeof(float)
                         + 2 * XRS * (int)sizeof(float);
    cudaFuncSetAttribute(fused_kernel, cudaFuncAttributeMaxDynamicSharedMemorySize,
                         fused_smem);

    prep_kernel<<<TT, H>>>(in, wq, Dv, os_out);
    scan0_kernel<<<dim3(8, NC), 256>>>(in, lam);
    combine_kernel<<<NELEM / 256, 256>>>(lam);
    fused_kernel<<<dim3(8, NC / CPC), 256, fused_smem>>>(in, lam, Cm, out);
}